// round 3
// baseline (speedup 1.0000x reference)
#include <cuda_runtime.h>
#include <math.h>

// Persistent scratch (zero-initialized at module load; last block resets them
// every call so graph replays are deterministic).
__device__ float        g_total;  // sum of ||err|| over ALL points, all batches
__device__ unsigned int g_count;  // block arrival counter

__device__ __forceinline__ void quat_to_rot(float qw, float qx, float qy, float qz, float* R) {
    float inv = rsqrtf(qw * qw + qx * qx + qy * qy + qz * qz);
    qw *= inv; qx *= inv; qy *= inv; qz *= inv;
    R[0] = 1.f - 2.f * (qy * qy + qz * qz);
    R[1] = 2.f * (qx * qy - qz * qw);
    R[2] = 2.f * (qx * qz + qy * qw);
    R[3] = 2.f * (qx * qy + qz * qw);
    R[4] = 1.f - 2.f * (qx * qx + qz * qz);
    R[5] = 2.f * (qy * qz - qx * qw);
    R[6] = 2.f * (qx * qz - qy * qw);
    R[7] = 2.f * (qy * qz + qx * qw);
    R[8] = 1.f - 2.f * (qx * qx + qy * qy);
}

// Fused kernel. grid = (blocksPerBatch, B), 256 threads.
// Each block: (a) recompute its batch transform A = Rp^T*Rt - I, t = Rp^T*(t_t - t_p)
// from the tiny pose inputs (redundant, ~100 FLOPs/thread, hidden under memory);
// (b) stream its slice of x/y/z rows (homogeneous row == 1 identically, never read);
// (c) block-reduce + atomicAdd into g_total. The LAST block to arrive computes the
// pose loss (one warp over B batches), combines, writes the 4 outputs, and resets
// the persistent scratch.
__global__ void __launch_bounds__(256) fused_kernel(
    const float* __restrict__ pc,
    const float* __restrict__ tgt_t,
    const float* __restrict__ tgt_r,
    const float* __restrict__ err_t,
    const float* __restrict__ err_r,
    float* __restrict__ out,
    int B, int N, unsigned int totalBlocks)
{
    int b = blockIdx.y;

    // ---- per-batch rigid transform (every thread, redundant) ----
    float Rt[9], Rp[9];
    quat_to_rot(tgt_r[4*b+0], tgt_r[4*b+1], tgt_r[4*b+2], tgt_r[4*b+3], Rt);
    quat_to_rot(err_r[4*b+0], err_r[4*b+1], err_r[4*b+2], err_r[4*b+3], Rp);

    float a00,a01,a02,a10,a11,a12,a20,a21,a22;
    {
        // C = Rp^T * Rt
        a00 = Rp[0]*Rt[0] + Rp[3]*Rt[3] + Rp[6]*Rt[6];
        a01 = Rp[0]*Rt[1] + Rp[3]*Rt[4] + Rp[6]*Rt[7];
        a02 = Rp[0]*Rt[2] + Rp[3]*Rt[5] + Rp[6]*Rt[8];
        a10 = Rp[1]*Rt[0] + Rp[4]*Rt[3] + Rp[7]*Rt[6];
        a11 = Rp[1]*Rt[1] + Rp[4]*Rt[4] + Rp[7]*Rt[7];
        a12 = Rp[1]*Rt[2] + Rp[4]*Rt[5] + Rp[7]*Rt[8];
        a20 = Rp[2]*Rt[0] + Rp[5]*Rt[3] + Rp[8]*Rt[6];
        a21 = Rp[2]*Rt[1] + Rp[5]*Rt[4] + Rp[8]*Rt[7];
        a22 = Rp[2]*Rt[2] + Rp[5]*Rt[5] + Rp[8]*Rt[8];
        a00 -= 1.f; a11 -= 1.f; a22 -= 1.f;   // A = C - I
    }
    float d0 = tgt_t[3*b+0] - err_t[3*b+0];
    float d1 = tgt_t[3*b+1] - err_t[3*b+1];
    float d2 = tgt_t[3*b+2] - err_t[3*b+2];
    float t0 = Rp[0]*d0 + Rp[3]*d1 + Rp[6]*d2;
    float t1 = Rp[1]*d0 + Rp[4]*d1 + Rp[7]*d2;
    float t2 = Rp[2]*d0 + Rp[5]*d1 + Rp[8]*d2;

    // ---- stream points ----
    const float* base = pc + (size_t)b * 4 * (size_t)N;
    float acc = 0.f;

    if ((N & 3) == 0) {
        int nvec = N >> 2;
        const float4* X = (const float4*)(base);
        const float4* Y = (const float4*)(base + N);
        const float4* Z = (const float4*)(base + 2 * (size_t)N);
        for (int i = blockIdx.x * blockDim.x + threadIdx.x; i < nvec;
             i += gridDim.x * blockDim.x) {
            float4 x = X[i];
            float4 y = Y[i];
            float4 z = Z[i];
            {
                float dx = fmaf(a00,x.x, fmaf(a01,y.x, fmaf(a02,z.x, t0)));
                float dy = fmaf(a10,x.x, fmaf(a11,y.x, fmaf(a12,z.x, t1)));
                float dz = fmaf(a20,x.x, fmaf(a21,y.x, fmaf(a22,z.x, t2)));
                acc += sqrtf(dx*dx + dy*dy + dz*dz);
            }
            {
                float dx = fmaf(a00,x.y, fmaf(a01,y.y, fmaf(a02,z.y, t0)));
                float dy = fmaf(a10,x.y, fmaf(a11,y.y, fmaf(a12,z.y, t1)));
                float dz = fmaf(a20,x.y, fmaf(a21,y.y, fmaf(a22,z.y, t2)));
                acc += sqrtf(dx*dx + dy*dy + dz*dz);
            }
            {
                float dx = fmaf(a00,x.z, fmaf(a01,y.z, fmaf(a02,z.z, t0)));
                float dy = fmaf(a10,x.z, fmaf(a11,y.z, fmaf(a12,z.z, t1)));
                float dz = fmaf(a20,x.z, fmaf(a21,y.z, fmaf(a22,z.z, t2)));
                acc += sqrtf(dx*dx + dy*dy + dz*dz);
            }
            {
                float dx = fmaf(a00,x.w, fmaf(a01,y.w, fmaf(a02,z.w, t0)));
                float dy = fmaf(a10,x.w, fmaf(a11,y.w, fmaf(a12,z.w, t1)));
                float dz = fmaf(a20,x.w, fmaf(a21,y.w, fmaf(a22,z.w, t2)));
                acc += sqrtf(dx*dx + dy*dy + dz*dz);
            }
        }
    } else {
        for (int n = blockIdx.x * blockDim.x + threadIdx.x; n < N;
             n += gridDim.x * blockDim.x) {
            float px = base[n], py = base[N + n], pz = base[2*(size_t)N + n];
            float dx = fmaf(a00,px, fmaf(a01,py, fmaf(a02,pz, t0)));
            float dy = fmaf(a10,px, fmaf(a11,py, fmaf(a12,pz, t1)));
            float dz = fmaf(a20,px, fmaf(a21,py, fmaf(a22,pz, t2)));
            acc += sqrtf(dx*dx + dy*dy + dz*dz);
        }
    }

    // ---- block reduction ----
    __shared__ float s[256];
    __shared__ int   s_last;
    s[threadIdx.x] = acc;
    __syncthreads();
    for (int st = blockDim.x >> 1; st >= 32; st >>= 1) {
        if (threadIdx.x < st) s[threadIdx.x] += s[threadIdx.x + st];
        __syncthreads();
    }
    if (threadIdx.x < 32) {
        float v = s[threadIdx.x];
        #pragma unroll
        for (int off = 16; off > 0; off >>= 1)
            v += __shfl_down_sync(0xFFFFFFFFu, v, off);
        if (threadIdx.x == 0) {
            atomicAdd(&g_total, v);
            __threadfence();
            unsigned prev = atomicAdd(&g_count, 1u);
            s_last = (prev == totalBlocks - 1u) ? 1 : 0;
        }
    }
    __syncthreads();

    // ---- last block: pose loss + combine + reset ----
    if (s_last) {
        float lt = 0.f, lr = 0.f;
        for (int bb = threadIdx.x; bb < B; bb += blockDim.x) {
            // Smooth-L1 translation loss
            #pragma unroll
            for (int k = 0; k < 3; k++) {
                float d = fabsf(err_t[3*bb+k] - tgt_t[3*bb+k]);
                lt += (d < 1.f) ? 0.5f*d*d : d - 0.5f;
            }
            // quaternion angular distance (degrees), on RAW quats (as reference)
            float q0 = err_r[4*bb+0], q1 = err_r[4*bb+1], q2 = err_r[4*bb+2], q3 = err_r[4*bb+3];
            float r0 = tgt_r[4*bb+0], r1 = -tgt_r[4*bb+1], r2 = -tgt_r[4*bb+2], r3 = -tgt_r[4*bb+3];
            float w = q0*r0 - q1*r1 - q2*r2 - q3*r3;
            float x = q0*r1 + q1*r0 + q2*r3 - q3*r2;
            float y = q0*r2 - q1*r3 + q2*r0 + q3*r1;
            float z = q0*r3 + q1*r2 - q2*r1 + q3*r0;
            float angle = 2.f * atan2f(sqrtf(x*x + y*y + z*z), fabsf(w));
            lr += angle * (180.f / 3.14159265358979323846f);
        }
        s[threadIdx.x] = lt;
        __syncthreads();
        __shared__ float s2[256];
        s2[threadIdx.x] = lr;
        __syncthreads();
        for (int st = blockDim.x >> 1; st > 0; st >>= 1) {
            if (threadIdx.x < st) {
                s[threadIdx.x]  += s[threadIdx.x + st];
                s2[threadIdx.x] += s2[threadIdx.x + st];
            }
            __syncthreads();
        }
        if (threadIdx.x == 0) {
            float loss_transl = s[0] / (float)B;
            float loss_rot    = s2[0] / (float)B;
            float pose_loss   = loss_transl + loss_rot;       // RESCALE_* = 1
            // g_total is complete: every block fenced before incrementing g_count.
            float total = *((volatile float*)&g_total);
            float pcl_over_B = (total / (float)N) / (float)B; // sum_b mean_b / B
            out[0] = 0.5f * pose_loss + 0.5f * pcl_over_B;    // WEIGHT_PC = 0.5
            out[1] = loss_transl;
            out[2] = loss_rot;
            out[3] = pcl_over_B;
            // reset persistent scratch for the next (graph-replayed) call
            g_total = 0.f;
            g_count = 0u;
            __threadfence();
        }
    }
}

extern "C" void kernel_launch(void* const* d_in, const int* in_sizes, int n_in,
                              void* d_out, int out_size) {
    const float* pc = (const float*)d_in[0];   // [B,4,N]
    const float* tt = (const float*)d_in[1];   // [B,3]
    const float* tr = (const float*)d_in[2];   // [B,4]
    const float* te = (const float*)d_in[3];   // [B,3]
    const float* re = (const float*)d_in[4];   // [B,4]

    int B = in_sizes[1] / 3;
    int N = in_sizes[0] / (4 * B);

    int nvec = (N + 3) >> 2;
    int blocksPerBatch = (nvec + 255) / 256;
    if (blocksPerBatch > 64) blocksPerBatch = 64;
    if (blocksPerBatch < 1) blocksPerBatch = 1;
    dim3 grid(blocksPerBatch, B);
    unsigned totalBlocks = (unsigned)blocksPerBatch * (unsigned)B;

    fused_kernel<<<grid, 256>>>(pc, tt, tr, te, re, (float*)d_out,
                                B, N, totalBlocks);
}